// round 3
// baseline (speedup 1.0000x reference)
#include <cuda_runtime.h>
#include <cuda_bf16.h>
#include <cstdint>

// Problem constants (shapes fixed by the dataset)
#define N_NODE   50000
#define N_EDGE   800000
#define F_IN     128
#define EDGE_DIM 16
#define HEADS    4
#define D_OUT    32
#define HD       (HEADS * D_OUT)   // 128

// ---------------- scratch (device globals; no runtime allocation) ----------
__device__ float g_xl [(size_t)N_NODE * HD];     // 25.6 MB
__device__ float g_xr [(size_t)N_NODE * HD];     // 25.6 MB
__device__ int   g_cnt [N_NODE];
__device__ int   g_off [N_NODE + 1];
__device__ int   g_cur [N_NODE];
__device__ int   g_perm[N_EDGE];

// ---------------- projection GEMM: x_l / x_r = nodes @ W ------------------
#define BM 64
#define BN 64
#define BK 8
__global__ __launch_bounds__(256) void gemm_kernel(
    const float* __restrict__ A,
    const float* __restrict__ Wl,
    const float* __restrict__ Wr,
    int M)
{
    const int byi = blockIdx.y;                 // 0..3
    const float* B = (byi < 2) ? Wl : Wr;
    float*       C = (byi < 2) ? g_xl : g_xr;
    const int cn0 = (byi & 1) * BN;
    const int rm0 = blockIdx.x * BM;

    __shared__ float As[BK][BM + 4];
    __shared__ float Bs[BK][BN];

    float acc[4][4];
#pragma unroll
    for (int i = 0; i < 4; i++)
#pragma unroll
        for (int j = 0; j < 4; j++) acc[i][j] = 0.f;

    const int tid = threadIdx.x;
    const int tx = tid & 15;
    const int ty = tid >> 4;

    const int li = tid * 2;
    const int ar = li / BK, ak = li % BK;
    const int bk = li / BN, bj = li % BN;

    for (int k0 = 0; k0 < F_IN; k0 += BK) {
        float2 av = make_float2(0.f, 0.f);
        if (rm0 + ar < M)
            av = *(const float2*)&A[(size_t)(rm0 + ar) * F_IN + k0 + ak];
        As[ak][ar]     = av.x;
        As[ak + 1][ar] = av.y;
        float2 bv = *(const float2*)&B[(size_t)(k0 + bk) * HD + cn0 + bj];
        Bs[bk][bj]     = bv.x;
        Bs[bk][bj + 1] = bv.y;
        __syncthreads();
#pragma unroll
        for (int k = 0; k < BK; k++) {
            float4 ra = *(const float4*)&As[k][ty * 4];
            float4 rb = *(const float4*)&Bs[k][tx * 4];
            float a_[4] = {ra.x, ra.y, ra.z, ra.w};
            float b_[4] = {rb.x, rb.y, rb.z, rb.w};
#pragma unroll
            for (int i = 0; i < 4; i++)
#pragma unroll
                for (int j = 0; j < 4; j++)
                    acc[i][j] = fmaf(a_[i], b_[j], acc[i][j]);
        }
        __syncthreads();
    }
#pragma unroll
    for (int i = 0; i < 4; i++) {
        int r = rm0 + ty * 4 + i;
        if (r < M) {
            float4 v = make_float4(acc[i][0], acc[i][1], acc[i][2], acc[i][3]);
            *(float4*)&C[(size_t)r * HD + cn0 + tx * 4] = v;
        }
    }
}

// ---------------- CSR build --------------------------------------------------
__global__ void zero_cnt_kernel(int N) {
    int i = blockIdx.x * blockDim.x + threadIdx.x;
    if (i < N) g_cnt[i] = 0;
}

__global__ void hist_kernel(const int* __restrict__ rcv, int E) {
    int e = blockIdx.x * blockDim.x + threadIdx.x;
    if (e < E) atomicAdd(&g_cnt[rcv[e]], 1);
}

// single-block hierarchical exclusive scan of g_cnt -> g_off (and g_cur copy)
__global__ __launch_bounds__(1024) void scan_kernel(int N, int E) {
    __shared__ int part[1024];
    const int t = threadIdx.x;
    const int chunk = (N + 1023) >> 10;
    const int lo = t * chunk;
    const int hi = min(lo + chunk, N);

    int s = 0;
    for (int i = lo; i < hi; i++) s += g_cnt[i];
    part[t] = s;
    __syncthreads();
    // inclusive Hillis-Steele scan
    for (int off = 1; off < 1024; off <<= 1) {
        int v = 0;
        if (t >= off) v = part[t - off];
        __syncthreads();
        if (t >= off) part[t] += v;
        __syncthreads();
    }
    int run = (t == 0) ? 0 : part[t - 1];
    for (int i = lo; i < hi; i++) {
        int c = g_cnt[i];
        g_off[i] = run;
        g_cur[i] = run;
        run += c;
    }
    if (t == 1023) g_off[N] = E;
}

__global__ void scatter_kernel(const int* __restrict__ rcv, int E) {
    int e = blockIdx.x * blockDim.x + threadIdx.x;
    if (e >= E) return;
    int pos = atomicAdd(&g_cur[rcv[e]], 1);
    g_perm[pos] = e;
}

// ---------------- warp-per-receiver fused scoring + aggregation -------------
// Lane ln owns columns c0=4*ln..4*ln+3 (head h = ln>>3). For each receiver:
// load x_r once, loop its edges: gather x_l[s], compute GATv2 logit
// (edge-proj in-register via shfl over the 16 edge features, leaky_relu,
// dot with attn_vec, 8-lane segmented reduce), exp, and accumulate
// exp * x_l into registers plus exp into the per-head denominator.
// Then normalize by (sum + 1e-8), average heads via shfl-xor(8,16), and
// write the final [N,32] output row directly. No atomics, no scratch output.
__global__ __launch_bounds__(256) void recv_agg_kernel(
    const int*   __restrict__ snd,
    const float* __restrict__ eattr,
    const float* __restrict__ We,
    const float* __restrict__ attn,
    float* __restrict__ out,
    int N)
{
    __shared__ float we_s[EDGE_DIM * HD];  // 8 KB
    __shared__ float at_s[HD];
    const int tid = threadIdx.x;
    for (int i = tid; i < EDGE_DIM * HD; i += 256) we_s[i] = We[i];
    if (tid < HD) at_s[tid] = attn[tid];
    __syncthreads();

    const int ln = tid & 31;
    const int c0 = ln * 4;
    const float4 at4 = *(const float4*)&at_s[c0];

    const int warps_total = gridDim.x * (blockDim.x >> 5);
    const int warp_id = blockIdx.x * (blockDim.x >> 5) + (tid >> 5);

    for (int n = warp_id; n < N; n += warps_total) {
        const int idx0 = g_off[n];
        const int idx1 = g_off[n + 1];

        float4 xr = *(const float4*)(g_xr + (size_t)n * HD + c0);
        float4 acc = make_float4(0.f, 0.f, 0.f, 0.f);
        float  ssum = 0.f;

        for (int idx = idx0; idx < idx1; idx++) {
            const int e = __ldg(&g_perm[idx]);
            const int s = __ldg(&snd[e]);

            float ea = (ln < EDGE_DIM) ? __ldg(&eattr[(size_t)e * EDGE_DIM + ln]) : 0.f;
            float4 xl = *(const float4*)(g_xl + (size_t)s * HD + c0);

            float4 ep = make_float4(0.f, 0.f, 0.f, 0.f);
#pragma unroll
            for (int k = 0; k < EDGE_DIM; k++) {
                float a = __shfl_sync(0xffffffffu, ea, k);
                float4 w = *(const float4*)&we_s[k * HD + c0];
                ep.x = fmaf(a, w.x, ep.x);
                ep.y = fmaf(a, w.y, ep.y);
                ep.z = fmaf(a, w.z, ep.z);
                ep.w = fmaf(a, w.w, ep.w);
            }

            float m0 = xl.x + xr.x + ep.x;
            float m1 = xl.y + xr.y + ep.y;
            float m2 = xl.z + xr.z + ep.z;
            float m3 = xl.w + xr.w + ep.w;
            // leaky_relu slope 0.2
            m0 = fmaxf(m0, 0.f) + 0.2f * fminf(m0, 0.f);
            m1 = fmaxf(m1, 0.f) + 0.2f * fminf(m1, 0.f);
            m2 = fmaxf(m2, 0.f) + 0.2f * fminf(m2, 0.f);
            m3 = fmaxf(m3, 0.f) + 0.2f * fminf(m3, 0.f);

            float p = fmaf(m0, at4.x, fmaf(m1, at4.y, fmaf(m2, at4.z, m3 * at4.w)));
            // 8-lane segmented reduce -> per-head logit
            p += __shfl_xor_sync(0xffffffffu, p, 4);
            p += __shfl_xor_sync(0xffffffffu, p, 2);
            p += __shfl_xor_sync(0xffffffffu, p, 1);

            // No max-subtraction: |logit| bounded (~12), exp safe in fp32;
            // exp(l)/sum(exp(l)) == softmax exactly.
            float ev = __expf(p);

            acc.x = fmaf(ev, xl.x, acc.x);
            acc.y = fmaf(ev, xl.y, acc.y);
            acc.z = fmaf(ev, xl.z, acc.z);
            acc.w = fmaf(ev, xl.w, acc.w);
            ssum += ev;
        }

        // normalize per head (ssum identical within each 8-lane head group)
        const float inv = 1.f / (ssum + 1e-8f);
        float4 w4 = make_float4(acc.x * inv, acc.y * inv, acc.z * inv, acc.w * inv);

        // sum across the 4 heads: lanes {p, p+8, p+16, p+24} hold the same d
        w4.x += __shfl_xor_sync(0xffffffffu, w4.x, 8);
        w4.y += __shfl_xor_sync(0xffffffffu, w4.y, 8);
        w4.z += __shfl_xor_sync(0xffffffffu, w4.z, 8);
        w4.w += __shfl_xor_sync(0xffffffffu, w4.w, 8);
        w4.x += __shfl_xor_sync(0xffffffffu, w4.x, 16);
        w4.y += __shfl_xor_sync(0xffffffffu, w4.y, 16);
        w4.z += __shfl_xor_sync(0xffffffffu, w4.z, 16);
        w4.w += __shfl_xor_sync(0xffffffffu, w4.w, 16);

        if (ln < 8) {
            float4 o = make_float4(0.25f * w4.x, 0.25f * w4.y,
                                   0.25f * w4.z, 0.25f * w4.w);
            *(float4*)&out[(size_t)n * D_OUT + ln * 4] = o;
        }
    }
}

// ---------------- launch -----------------------------------------------------
extern "C" void kernel_launch(void* const* d_in, const int* in_sizes, int n_in,
                              void* d_out, int out_size)
{
    const float* nodes = (const float*)d_in[0];
    const int*   snd   = (const int*)  d_in[1];
    const int*   rcv   = (const int*)  d_in[2];
    const float* eattr = (const float*)d_in[3];
    int wbase = (in_sizes[4] == 1) ? 5 : 4;
    const float* Wl   = (const float*)d_in[wbase + 0];
    const float* Wr   = (const float*)d_in[wbase + 1];
    const float* We   = (const float*)d_in[wbase + 2];
    const float* attn = (const float*)d_in[wbase + 3];

    const int N = in_sizes[0] / F_IN;
    const int E = in_sizes[1];

    // CSR build (receiver-sorted edge permutation)
    zero_cnt_kernel<<<(N + 255) / 256, 256>>>(N);
    hist_kernel<<<(E + 255) / 256, 256>>>(rcv, E);
    scan_kernel<<<1, 1024>>>(N, E);
    scatter_kernel<<<(E + 255) / 256, 256>>>(rcv, E);

    // projections
    dim3 gg((N + BM - 1) / BM, 4);
    gemm_kernel<<<gg, 256>>>(nodes, Wl, Wr, N);

    // fused score + aggregate + normalize + head-mean
    recv_agg_kernel<<<1184, 256>>>(snd, eattr, We, attn, (float*)d_out, N);
}